// round 1
// baseline (speedup 1.0000x reference)
#include <cuda_runtime.h>
#include <math.h>

// Image is fixed 3 x 2048 x 2048 float32, fixs is 4 x 2 float32.
#define HH 2048
#define WW 2048
#define HWFULL (HH * WW)
#define NE 1024              // E maps (half-res expansions) are 1024x1024

// ---------------- static scratch (no allocations allowed) ----------------
__device__ float g_pyr1[3 * 1024 * 1024];
__device__ float g_pyr2[3 * 512 * 512];
__device__ float g_pyr3[3 * 256 * 256];
__device__ float g_pyr4[3 * 128 * 128];
__device__ float g_pyr5[3 * 64 * 64];
__device__ float g_E2[3 * 1024 * 1024];
__device__ float g_E3[3 * 1024 * 1024];
__device__ float g_E4[3 * 1024 * 1024];
__device__ float g_E5[3 * 1024 * 1024];
__device__ float g_t3a[3 * 512 * 512];
__device__ float g_t4a[3 * 256 * 256];
__device__ float g_t4b[3 * 512 * 512];
__device__ float g_t5a[3 * 128 * 128];
__device__ float g_t5b[3 * 256 * 256];
__device__ float g_t5c[3 * 512 * 512];

// ---------------- fused blur (separable 3-tap) + 2x2 mean downsample ------
// out[i] = 0.5*(b[2i] + b[2i+1]) per dim with b = zero-padded blur.
// Combined taps on input positions {2i-1, 2i, 2i+1, 2i+2}: {De, Dm, Dm, De}.
__global__ void blur_down_kernel(const float* __restrict__ in, float* __restrict__ out,
                                 int no, float De, float Dm) {
    int x = blockIdx.x * blockDim.x + threadIdx.x;
    int y = blockIdx.y * blockDim.y + threadIdx.y;
    int c = blockIdx.z;
    if (x >= no || y >= no) return;
    int ni = 2 * no;
    const float* ip = in + (size_t)c * ni * ni;
    float wt[4] = {De, Dm, Dm, De};
    float acc = 0.f;
#pragma unroll
    for (int jy = 0; jy < 4; jy++) {
        int ry = 2 * y - 1 + jy;
        if (ry < 0 || ry >= ni) continue;   // zero padding of the blur
        const float* row = ip + (size_t)ry * ni;
        float rs = 0.f;
#pragma unroll
        for (int jx = 0; jx < 4; jx++) {
            int cx = 2 * x - 1 + jx;
            if (cx < 0 || cx >= ni) continue;
            rs += wt[jx] * row[cx];
        }
        acc += wt[jy] * rs;
    }
    out[(size_t)c * no * no + (size_t)y * no + x] = acc;
}

// ---------------- composite (bilinear x2 upsample -> 3-tap blur) weights ---
// For output index o (output size 2n), the result depends on input indices
// {o/2-1, o/2, o/2+1} (clamped). Blur taps falling outside [0,2n) are dropped
// (zero padding); bilinear indices outside [0,n) are clamped (resize semantics).
__device__ __forceinline__ void ub_weights(int o, int n, float w0, float w1,
                                           int& base, float w[3]) {
    base = (o >> 1) - 1;
    w[0] = w[1] = w[2] = 0.f;
    int n2 = n * 2;
#pragma unroll
    for (int d = -1; d <= 1; ++d) {
        int p = o + d;
        if (p < 0 || p >= n2) continue;
        float bw = (d == 0) ? w0 : w1;
        int i = p >> 1;
        if ((p & 1) == 0) {                 // up[2i] = 0.25*E[i-1] + 0.75*E[i]
            w[i - 1 - base] += 0.25f * bw;
            w[i - base]     += 0.75f * bw;
        } else {                            // up[2i+1] = 0.75*E[i] + 0.25*E[i+1]
            w[i - base]     += 0.75f * bw;
            w[i + 1 - base] += 0.25f * bw;
        }
    }
}

// ---------------- staged up+blur kernel (several independent tasks) --------
struct UpTasks {
    const float* in[4];
    float* out[4];
    int n[4];
};

__global__ void up_blur_kernel(UpTasks T, float w0, float w1) {
    int task = blockIdx.z / 3;
    int c = blockIdx.z - task * 3;
    int n = T.n[task];
    int no = 2 * n;
    int ox = blockIdx.x * blockDim.x + threadIdx.x;
    int oy = blockIdx.y * blockDim.y + threadIdx.y;
    if (ox >= no || oy >= no) return;
    const float* E = T.in[task] + (size_t)c * n * n;

    int by, bx;
    float wy[3], wx[3];
    ub_weights(oy, n, w0, w1, by, wy);
    ub_weights(ox, n, w0, w1, bx, wx);
    int ry[3], rx[3];
#pragma unroll
    for (int j = 0; j < 3; j++) {
        ry[j] = min(max(by + j, 0), n - 1);
        rx[j] = min(max(bx + j, 0), n - 1);
    }
    float s = 0.f;
#pragma unroll
    for (int jy = 0; jy < 3; jy++) {
        const float* row = E + (size_t)ry[jy] * n;
        s += wy[jy] * (wx[0] * row[rx[0]] + wx[1] * row[rx[1]] + wx[2] * row[rx[2]]);
    }
    T.out[task][(size_t)c * no * no + (size_t)oy * no + ox] = s;
}

// ---------------- final blend: per pixel, only 2 pyramid levels matter -----
__global__ void blend_kernel(const float* __restrict__ img, const float* __restrict__ fixs,
                             const float* __restrict__ E1, const float* __restrict__ E2,
                             const float* __restrict__ E3, const float* __restrict__ E4,
                             const float* __restrict__ E5, float* __restrict__ out,
                             float w0, float w1,
                             float om0, float om1, float om2, float om3, float om4) {
    int x = blockIdx.x * blockDim.x + threadIdx.x;
    int y = blockIdx.y * blockDim.y + threadIdx.y;
    if (x >= WW || y >= HH) return;

    float xf = (float)x, yf = (float)y;
    float d2 = 3.4e38f;
#pragma unroll
    for (int k = 0; k < 4; k++) {
        float dx = xf - fixs[2 * k];
        float dy = yf - fixs[2 * k + 1];
        float dd = dx * dx + dy * dy;
        d2 = fminf(d2, dd);
    }
    float theta = sqrtf(d2) / 7.5f;
    float R = 2.5f / (theta + 2.5f);

    float omega[6] = {om0, om1, om2, om3, om4, 0.f};
    int l = 0;
#pragma unroll
    for (int i = 1; i <= 5; i++)
        if (R >= omega[i] && R <= omega[i - 1]) l = i;

    int pix = y * WW + x;
    if (l == 0) {   // M0 = 1: pass-through
        out[pix] = img[pix];
        out[pix + HWFULL] = img[pix + HWFULL];
        out[pix + 2 * HWFULL] = img[pix + 2 * HWFULL];
        return;
    }

    // B = Bs[l-1] = (0.5 - Ts[l]) / (Ts[l-1] - Ts[l] + 1e-5), Ts[5] = 0
    float sprev = exp2f((float)(l - 3));
    float ap = sprev * R / 0.248f;
    float tp = expf(-(ap * ap) * 3.0f);
    float tc = 0.f;
    if (l < 5) {
        float ac = (2.f * sprev) * R / 0.248f;
        tc = expf(-(ac * ac) * 3.0f);
    }
    float B = (0.5f - tc) / (tp - tc + 1e-5f);

    // evaluate As[l] (and As[l-1]) = up+blur of the half-res E maps, inline
    int by, bx;
    float wy[3], wx[3];
    ub_weights(y, NE, w0, w1, by, wy);
    ub_weights(x, NE, w0, w1, bx, wx);
    int ry[3], rx[3];
#pragma unroll
    for (int j = 0; j < 3; j++) {
        ry[j] = min(max(by + j, 0), NE - 1);
        rx[j] = min(max(bx + j, 0), NE - 1);
    }
    const float* Elist[5] = {E1, E2, E3, E4, E5};
    const float* Ecur = Elist[l - 1];
    const float* Eprev = (l >= 2) ? Elist[l - 2] : 0;

#pragma unroll
    for (int c = 0; c < 3; c++) {
        int coff = c * NE * NE;
        float vc = 0.f;
#pragma unroll
        for (int jy = 0; jy < 3; jy++) {
            const float* row = Ecur + coff + ry[jy] * NE;
            vc += wy[jy] * (wx[0] * row[rx[0]] + wx[1] * row[rx[1]] + wx[2] * row[rx[2]]);
        }
        float vp;
        if (l == 1) {
            vp = img[pix + c * HWFULL];
        } else {
            vp = 0.f;
#pragma unroll
            for (int jy = 0; jy < 3; jy++) {
                const float* row = Eprev + coff + ry[jy] * NE;
                vp += wy[jy] * (wx[0] * row[rx[0]] + wx[1] * row[rx[1]] + wx[2] * row[rx[2]]);
            }
        }
        out[pix + c * HWFULL] = B * vp + (1.f - B) * vc;
    }
}

// ---------------- host launch ---------------------------------------------
extern "C" void kernel_launch(void* const* d_in, const int* in_sizes, int n_in,
                              void* d_out, int out_size) {
    const float* img = (const float*)d_in[0];
    const float* fixs = (const float*)d_in[1];
    float* out = (float*)d_out;

    float *pyr1, *pyr2, *pyr3, *pyr4, *pyr5, *E2, *E3, *E4, *E5;
    float *t3a, *t4a, *t4b, *t5a, *t5b, *t5c;
    cudaGetSymbolAddress((void**)&pyr1, g_pyr1);
    cudaGetSymbolAddress((void**)&pyr2, g_pyr2);
    cudaGetSymbolAddress((void**)&pyr3, g_pyr3);
    cudaGetSymbolAddress((void**)&pyr4, g_pyr4);
    cudaGetSymbolAddress((void**)&pyr5, g_pyr5);
    cudaGetSymbolAddress((void**)&E2, g_E2);
    cudaGetSymbolAddress((void**)&E3, g_E3);
    cudaGetSymbolAddress((void**)&E4, g_E4);
    cudaGetSymbolAddress((void**)&E5, g_E5);
    cudaGetSymbolAddress((void**)&t3a, g_t3a);
    cudaGetSymbolAddress((void**)&t4a, g_t4a);
    cudaGetSymbolAddress((void**)&t4b, g_t4b);
    cudaGetSymbolAddress((void**)&t5a, g_t5a);
    cudaGetSymbolAddress((void**)&t5b, g_t5b);
    cudaGetSymbolAddress((void**)&t5c, g_t5c);

    // Gaussian taps (w2 ~ 7.5e-15 dropped from taps; kept in normalization)
    double s2 = 2.0 * 0.248 * 0.248;
    double g1 = exp(-1.0 / s2);
    double g2 = exp(-4.0 / s2);
    double nrm = 1.0 + 2.0 * g1 + 2.0 * g2;
    float w0 = (float)(1.0 / nrm);
    float w1 = (float)(g1 / nrm);
    float De = (float)(0.5 * g1 / nrm);
    float Dm = (float)(0.5 * (1.0 + g1) / nrm);

    double ob = sqrt(log(2.0) / 3.0) * 0.248;
    float om0 = (float)(ob * 4.0);
    float om1 = (float)(ob * 2.0);
    float om2 = (float)(ob);
    float om3 = (float)(ob * 0.5);
    float om4 = (float)(ob * 0.25);

    dim3 blk(32, 8);
    auto grd = [](int n) { return dim3((n + 31) / 32, (n + 7) / 8, 3); };

    // Gaussian pyramid (fused blur + 2x2 mean)
    blur_down_kernel<<<grd(1024), blk>>>(img,  pyr1, 1024, De, Dm);
    blur_down_kernel<<<grd(512),  blk>>>(pyr1, pyr2, 512,  De, Dm);
    blur_down_kernel<<<grd(256),  blk>>>(pyr2, pyr3, 256,  De, Dm);
    blur_down_kernel<<<grd(128),  blk>>>(pyr3, pyr4, 128,  De, Dm);
    blur_down_kernel<<<grd(64),   blk>>>(pyr4, pyr5, 64,   De, Dm);

    // Expansion chains to 1024x1024 (E maps), staged so independent steps share a launch
    UpTasks A; A.in[0] = pyr2; A.out[0] = E2;  A.n[0] = 512;
               A.in[1] = pyr3; A.out[1] = t3a; A.n[1] = 256;
               A.in[2] = pyr4; A.out[2] = t4a; A.n[2] = 128;
               A.in[3] = pyr5; A.out[3] = t5a; A.n[3] = 64;
    up_blur_kernel<<<dim3(32, 128, 12), blk>>>(A, w0, w1);

    UpTasks B; B.in[0] = t3a; B.out[0] = E3;  B.n[0] = 512;
               B.in[1] = t4a; B.out[1] = t4b; B.n[1] = 256;
               B.in[2] = t5a; B.out[2] = t5b; B.n[2] = 128;
               B.in[3] = 0;   B.out[3] = 0;   B.n[3] = 1;
    up_blur_kernel<<<dim3(32, 128, 9), blk>>>(B, w0, w1);

    UpTasks C; C.in[0] = t4b; C.out[0] = E4;  C.n[0] = 512;
               C.in[1] = t5b; C.out[1] = t5c; C.n[1] = 256;
               C.in[2] = 0;   C.out[2] = 0;   C.n[2] = 1;
               C.in[3] = 0;   C.out[3] = 0;   C.n[3] = 1;
    up_blur_kernel<<<dim3(32, 128, 6), blk>>>(C, w0, w1);

    UpTasks D; D.in[0] = t5c; D.out[0] = E5;  D.n[0] = 512;
               D.in[1] = 0;   D.out[1] = 0;   D.n[1] = 1;
               D.in[2] = 0;   D.out[2] = 0;   D.n[2] = 1;
               D.in[3] = 0;   D.out[3] = 0;   D.n[3] = 1;
    up_blur_kernel<<<dim3(32, 128, 3), blk>>>(D, w0, w1);

    // Final blend (only the 2 relevant levels per pixel, up+blur inlined)
    blend_kernel<<<dim3(WW / 32, HH / 8), blk>>>(img, fixs, pyr1, E2, E3, E4, E5, out,
                                                 w0, w1, om0, om1, om2, om3, om4);
}

// round 2
// speedup vs baseline: 1.1223x; 1.1223x over previous
#include <cuda_runtime.h>
#include <math.h>

#define HH 2048
#define WW 2048
#define HWFULL (HH * WW)
#define NE 1024              // E maps (half-res expansions) are 1024x1024

// ---------------- static scratch (no allocations allowed) ----------------
__device__ float g_pyr1[3 * 1024 * 1024];
__device__ float g_pyr2[3 * 512 * 512];
__device__ float g_pyr3[3 * 256 * 256];
__device__ float g_pyr4[3 * 128 * 128];
__device__ float g_pyr5[3 * 64 * 64];
__device__ float g_E2[3 * 1024 * 1024];
__device__ float g_E3[3 * 1024 * 1024];
__device__ float g_E4[3 * 1024 * 1024];
__device__ float g_E5[3 * 1024 * 1024];
__device__ float g_t3a[3 * 512 * 512];
__device__ float g_t4a[3 * 256 * 256];
__device__ float g_t4b[3 * 512 * 512];
__device__ float g_t5a[3 * 128 * 128];
__device__ float g_t5b[3 * 256 * 256];
__device__ float g_t5c[3 * 512 * 512];

// ---------------- fused blur (separable 3-tap) + 2x2 mean downsample ------
__global__ void blur_down_kernel(const float* __restrict__ in, float* __restrict__ out,
                                 int no, float De, float Dm) {
    int x = blockIdx.x * blockDim.x + threadIdx.x;
    int y = blockIdx.y * blockDim.y + threadIdx.y;
    int c = blockIdx.z;
    if (x >= no || y >= no) return;
    int ni = 2 * no;
    const float* ip = in + (size_t)c * ni * ni;
    float wt[4] = {De, Dm, Dm, De};
    float acc = 0.f;
#pragma unroll
    for (int jy = 0; jy < 4; jy++) {
        int ry = 2 * y - 1 + jy;
        if (ry < 0 || ry >= ni) continue;
        const float* row = ip + (size_t)ry * ni;
        float rs = 0.f;
#pragma unroll
        for (int jx = 0; jx < 4; jx++) {
            int cx = 2 * x - 1 + jx;
            if (cx < 0 || cx >= ni) continue;
            rs += wt[jx] * row[cx];
        }
        acc += wt[jy] * rs;
    }
    out[(size_t)c * no * no + (size_t)y * no + x] = acc;
}

// ---------------- composite (bilinear x2 upsample -> 3-tap blur) weights ---
__device__ __forceinline__ void ub_weights(int o, int n, float w0, float w1,
                                           int& base, float w[3]) {
    base = (o >> 1) - 1;
    w[0] = w[1] = w[2] = 0.f;
    int n2 = n * 2;
#pragma unroll
    for (int d = -1; d <= 1; ++d) {
        int p = o + d;
        if (p < 0 || p >= n2) continue;
        float bw = (d == 0) ? w0 : w1;
        int i = p >> 1;
        if ((p & 1) == 0) {
            w[i - 1 - base] += 0.25f * bw;
            w[i - base]     += 0.75f * bw;
        } else {
            w[i - base]     += 0.75f * bw;
            w[i + 1 - base] += 0.25f * bw;
        }
    }
}

// ---------------- staged up+blur kernel (several independent tasks) --------
struct UpTasks {
    const float* in[4];
    float* out[4];
    int n[4];
};

__global__ void up_blur_kernel(UpTasks T, float w0, float w1) {
    int task = blockIdx.z / 3;
    int c = blockIdx.z - task * 3;
    int n = T.n[task];
    int no = 2 * n;
    int ox = blockIdx.x * blockDim.x + threadIdx.x;
    int oy = blockIdx.y * blockDim.y + threadIdx.y;
    if (ox >= no || oy >= no) return;
    const float* E = T.in[task] + (size_t)c * n * n;

    int by, bx;
    float wy[3], wx[3];
    ub_weights(oy, n, w0, w1, by, wy);
    ub_weights(ox, n, w0, w1, bx, wx);
    int ry[3], rx[3];
#pragma unroll
    for (int j = 0; j < 3; j++) {
        ry[j] = min(max(by + j, 0), n - 1);
        rx[j] = min(max(bx + j, 0), n - 1);
    }
    float s = 0.f;
#pragma unroll
    for (int jy = 0; jy < 3; jy++) {
        const float* row = E + (size_t)ry[jy] * n;
        s += wy[jy] * (wx[0] * row[rx[0]] + wx[1] * row[rx[1]] + wx[2] * row[rx[2]]);
    }
    T.out[task][(size_t)c * no * no + (size_t)oy * no + ox] = s;
}

// ---------------- blend helpers --------------------------------------------
__device__ __forceinline__ const float* level_ptr(int l, const float* E1, const float* E2,
                                                  const float* E3, const float* E4,
                                                  const float* E5) {
    // branch-free select chain (stays in registers, no local memory)
    const float* p = E1;
    p = (l == 2) ? E2 : p;
    p = (l == 3) ? E3 : p;
    p = (l == 4) ? E4 : p;
    p = (l == 5) ? E5 : p;
    return p;
}

__device__ __forceinline__ float blend_B(int l, float R) {
    float sprev = exp2f((float)(l - 3));
    float ap = sprev * R * (1.0f / 0.248f);
    float tp = expf(-(ap * ap) * 3.0f);
    float tc = 0.f;
    if (l < 5) {
        float ac = 2.0f * ap;
        tc = expf(-(ac * ac) * 3.0f);
    }
    return (0.5f - tc) / (tp - tc + 1e-5f);
}

// per-pixel general path (borders / mixed-level quads) — same math as R1 kernel
__device__ void pixel_slow(int x, int y, int l, float R,
                           const float* __restrict__ img,
                           const float* __restrict__ E1, const float* __restrict__ E2,
                           const float* __restrict__ E3, const float* __restrict__ E4,
                           const float* __restrict__ E5, float* __restrict__ out,
                           float w0, float w1) {
    int pix = y * WW + x;
    if (l == 0) {
        out[pix] = img[pix];
        out[pix + HWFULL] = img[pix + HWFULL];
        out[pix + 2 * HWFULL] = img[pix + 2 * HWFULL];
        return;
    }
    float B = blend_B(l, R);

    int by, bx;
    float wy[3], wx[3];
    ub_weights(y, NE, w0, w1, by, wy);
    ub_weights(x, NE, w0, w1, bx, wx);
    int ry[3], rx[3];
#pragma unroll
    for (int j = 0; j < 3; j++) {
        ry[j] = min(max(by + j, 0), NE - 1);
        rx[j] = min(max(bx + j, 0), NE - 1);
    }
    const float* Ecur = level_ptr(l, E1, E2, E3, E4, E5);
    const float* Eprev = level_ptr(l - 1, E1, E2, E3, E4, E5);

#pragma unroll
    for (int c = 0; c < 3; c++) {
        int coff = c * NE * NE;
        float vc = 0.f;
#pragma unroll
        for (int jy = 0; jy < 3; jy++) {
            const float* row = Ecur + coff + ry[jy] * NE;
            vc += wy[jy] * (wx[0] * row[rx[0]] + wx[1] * row[rx[1]] + wx[2] * row[rx[2]]);
        }
        float vp;
        if (l == 1) {
            vp = img[pix + c * HWFULL];
        } else {
            vp = 0.f;
#pragma unroll
            for (int jy = 0; jy < 3; jy++) {
                const float* row = Eprev + coff + ry[jy] * NE;
                vp += wy[jy] * (wx[0] * row[rx[0]] + wx[1] * row[rx[1]] + wx[2] * row[rx[2]]);
            }
        }
        out[pix + c * HWFULL] = B * vp + (1.f - B) * vc;
    }
}

// ---------------- quad blend: one thread handles a 2x2 output quad ---------
// All 4 pixels share the SAME 3x3 E-map window (base = q-1). Interior pixels
// have parity-constant composite weights we[3] (even) / reversed (odd).
__global__ __launch_bounds__(256)
void blend_quad_kernel(const float* __restrict__ img, const float* __restrict__ fixs,
                       const float* __restrict__ E1, const float* __restrict__ E2,
                       const float* __restrict__ E3, const float* __restrict__ E4,
                       const float* __restrict__ E5, float* __restrict__ out,
                       float w0, float w1, float we0, float we1, float we2,
                       float om0, float om1, float om2, float om3, float om4) {
    int qx = blockIdx.x * blockDim.x + threadIdx.x;
    int qy = blockIdx.y * blockDim.y + threadIdx.y;
    if (qx >= NE || qy >= NE) return;

    float fx[4], fy[4];
#pragma unroll
    for (int k = 0; k < 4; k++) { fx[k] = fixs[2 * k]; fy[k] = fixs[2 * k + 1]; }

    float omega[6] = {om0, om1, om2, om3, om4, 0.f};
    int lv[2][2];
    float Rv[2][2];
#pragma unroll
    for (int py = 0; py < 2; py++) {
#pragma unroll
        for (int px = 0; px < 2; px++) {
            float xf = (float)(2 * qx + px), yf = (float)(2 * qy + py);
            float d2 = 3.4e38f;
#pragma unroll
            for (int k = 0; k < 4; k++) {
                float dx = xf - fx[k], dy = yf - fy[k];
                d2 = fminf(d2, dx * dx + dy * dy);
            }
            float theta = sqrtf(d2) * (1.0f / 7.5f);
            float R = 2.5f / (theta + 2.5f);
            Rv[py][px] = R;
            int l = 0;
#pragma unroll
            for (int i = 1; i <= 5; i++)
                if (R >= omega[i] && R <= omega[i - 1]) l = i;
            lv[py][px] = l;
        }
    }

    int l0 = lv[0][0];
    bool uni = (lv[0][1] == l0) && (lv[1][0] == l0) && (lv[1][1] == l0);
    int pix0 = (2 * qy) * WW + 2 * qx;

    if (uni && l0 == 0) {
        // pass-through quad (border-safe)
#pragma unroll
        for (int c = 0; c < 3; c++) {
            const float2* ir0 = (const float2*)(img + pix0 + c * HWFULL);
            const float2* ir1 = (const float2*)(img + pix0 + WW + c * HWFULL);
            float2* or0 = (float2*)(out + pix0 + c * HWFULL);
            float2* or1 = (float2*)(out + pix0 + WW + c * HWFULL);
            or0[0] = ir0[0];
            or1[0] = ir1[0];
        }
        return;
    }

    bool border = (qx == 0) | (qx >= NE - 1) | (qy == 0) | (qy >= NE - 1);
    if (!uni || border) {
#pragma unroll
        for (int py = 0; py < 2; py++)
#pragma unroll
            for (int px = 0; px < 2; px++)
                pixel_slow(2 * qx + px, 2 * qy + py, lv[py][px], Rv[py][px],
                           img, E1, E2, E3, E4, E5, out, w0, w1);
        return;
    }

    // ---- fast path: uniform level, interior quad ----
    float B[2][2];
#pragma unroll
    for (int py = 0; py < 2; py++)
#pragma unroll
        for (int px = 0; px < 2; px++)
            B[py][px] = blend_B(l0, Rv[py][px]);

    const float* cur = level_ptr(l0, E1, E2, E3, E4, E5);
    const float* prv = level_ptr(l0 - 1, E1, E2, E3, E4, E5);  // unused if l0==1
    int wbase = (qy - 1) * NE + (qx - 1);

#pragma unroll
    for (int c = 0; c < 3; c++) {
        const float* pc = cur + c * NE * NE + wbase;
        // 3x3 current-level window -> separable parity combos
        float he[3], ho[3];
#pragma unroll
        for (int j = 0; j < 3; j++) {
            float a = pc[j * NE], b = pc[j * NE + 1], d = pc[j * NE + 2];
            he[j] = we0 * a + we1 * b + we2 * d;
            ho[j] = we2 * a + we1 * b + we0 * d;
        }
        float vc[2][2];
        vc[0][0] = we0 * he[0] + we1 * he[1] + we2 * he[2];
        vc[0][1] = we0 * ho[0] + we1 * ho[1] + we2 * ho[2];
        vc[1][0] = we2 * he[0] + we1 * he[1] + we0 * he[2];
        vc[1][1] = we2 * ho[0] + we1 * ho[1] + we0 * ho[2];

        float vp[2][2];
        if (l0 == 1) {
            float2 i0 = *(const float2*)(img + pix0 + c * HWFULL);
            float2 i1 = *(const float2*)(img + pix0 + WW + c * HWFULL);
            vp[0][0] = i0.x; vp[0][1] = i0.y; vp[1][0] = i1.x; vp[1][1] = i1.y;
        } else {
            const float* pp = prv + c * NE * NE + wbase;
            float pe[3], po[3];
#pragma unroll
            for (int j = 0; j < 3; j++) {
                float a = pp[j * NE], b = pp[j * NE + 1], d = pp[j * NE + 2];
                pe[j] = we0 * a + we1 * b + we2 * d;
                po[j] = we2 * a + we1 * b + we0 * d;
            }
            vp[0][0] = we0 * pe[0] + we1 * pe[1] + we2 * pe[2];
            vp[0][1] = we0 * po[0] + we1 * po[1] + we2 * po[2];
            vp[1][0] = we2 * pe[0] + we1 * pe[1] + we0 * pe[2];
            vp[1][1] = we2 * po[0] + we1 * po[1] + we0 * po[2];
        }

        float2 o0, o1;
        o0.x = B[0][0] * vp[0][0] + (1.f - B[0][0]) * vc[0][0];
        o0.y = B[0][1] * vp[0][1] + (1.f - B[0][1]) * vc[0][1];
        o1.x = B[1][0] * vp[1][0] + (1.f - B[1][0]) * vc[1][0];
        o1.y = B[1][1] * vp[1][1] + (1.f - B[1][1]) * vc[1][1];
        *(float2*)(out + pix0 + c * HWFULL) = o0;
        *(float2*)(out + pix0 + WW + c * HWFULL) = o1;
    }
}

// ---------------- host launch ---------------------------------------------
extern "C" void kernel_launch(void* const* d_in, const int* in_sizes, int n_in,
                              void* d_out, int out_size) {
    const float* img = (const float*)d_in[0];
    const float* fixs = (const float*)d_in[1];
    float* out = (float*)d_out;

    float *pyr1, *pyr2, *pyr3, *pyr4, *pyr5, *E2, *E3, *E4, *E5;
    float *t3a, *t4a, *t4b, *t5a, *t5b, *t5c;
    cudaGetSymbolAddress((void**)&pyr1, g_pyr1);
    cudaGetSymbolAddress((void**)&pyr2, g_pyr2);
    cudaGetSymbolAddress((void**)&pyr3, g_pyr3);
    cudaGetSymbolAddress((void**)&pyr4, g_pyr4);
    cudaGetSymbolAddress((void**)&pyr5, g_pyr5);
    cudaGetSymbolAddress((void**)&E2, g_E2);
    cudaGetSymbolAddress((void**)&E3, g_E3);
    cudaGetSymbolAddress((void**)&E4, g_E4);
    cudaGetSymbolAddress((void**)&E5, g_E5);
    cudaGetSymbolAddress((void**)&t3a, g_t3a);
    cudaGetSymbolAddress((void**)&t4a, g_t4a);
    cudaGetSymbolAddress((void**)&t4b, g_t4b);
    cudaGetSymbolAddress((void**)&t5a, g_t5a);
    cudaGetSymbolAddress((void**)&t5b, g_t5b);
    cudaGetSymbolAddress((void**)&t5c, g_t5c);

    // Gaussian taps (w2 ~ 7.5e-15 dropped from taps; kept in normalization)
    double s2 = 2.0 * 0.248 * 0.248;
    double g1 = exp(-1.0 / s2);
    double g2 = exp(-4.0 / s2);
    double nrm = 1.0 + 2.0 * g1 + 2.0 * g2;
    float w0 = (float)(1.0 / nrm);
    float w1 = (float)(g1 / nrm);
    float De = (float)(0.5 * g1 / nrm);
    float Dm = (float)(0.5 * (1.0 + g1) / nrm);
    // interior composite (upsample x2 -> blur) parity weights
    float we0 = 0.25f * w0 + 0.75f * w1;
    float we1 = 0.75f * w0 + w1;
    float we2 = 0.25f * w1;

    double ob = sqrt(log(2.0) / 3.0) * 0.248;
    float om0 = (float)(ob * 4.0);
    float om1 = (float)(ob * 2.0);
    float om2 = (float)(ob);
    float om3 = (float)(ob * 0.5);
    float om4 = (float)(ob * 0.25);

    dim3 blk(32, 8);
    auto grd = [](int n) { return dim3((n + 31) / 32, (n + 7) / 8, 3); };

    // Gaussian pyramid (fused blur + 2x2 mean)
    blur_down_kernel<<<grd(1024), blk>>>(img,  pyr1, 1024, De, Dm);
    blur_down_kernel<<<grd(512),  blk>>>(pyr1, pyr2, 512,  De, Dm);
    blur_down_kernel<<<grd(256),  blk>>>(pyr2, pyr3, 256,  De, Dm);
    blur_down_kernel<<<grd(128),  blk>>>(pyr3, pyr4, 128,  De, Dm);
    blur_down_kernel<<<grd(64),   blk>>>(pyr4, pyr5, 64,   De, Dm);

    // Expansion chains to 1024x1024 (E maps), staged
    UpTasks A; A.in[0] = pyr2; A.out[0] = E2;  A.n[0] = 512;
               A.in[1] = pyr3; A.out[1] = t3a; A.n[1] = 256;
               A.in[2] = pyr4; A.out[2] = t4a; A.n[2] = 128;
               A.in[3] = pyr5; A.out[3] = t5a; A.n[3] = 64;
    up_blur_kernel<<<dim3(32, 128, 12), blk>>>(A, w0, w1);

    UpTasks B; B.in[0] = t3a; B.out[0] = E3;  B.n[0] = 512;
               B.in[1] = t4a; B.out[1] = t4b; B.n[1] = 256;
               B.in[2] = t5a; B.out[2] = t5b; B.n[2] = 128;
               B.in[3] = 0;   B.out[3] = 0;   B.n[3] = 1;
    up_blur_kernel<<<dim3(32, 128, 9), blk>>>(B, w0, w1);

    UpTasks C; C.in[0] = t4b; C.out[0] = E4;  C.n[0] = 512;
               C.in[1] = t5b; C.out[1] = t5c; C.n[1] = 256;
               C.in[2] = 0;   C.out[2] = 0;   C.n[2] = 1;
               C.in[3] = 0;   C.out[3] = 0;   C.n[3] = 1;
    up_blur_kernel<<<dim3(32, 128, 6), blk>>>(C, w0, w1);

    UpTasks D; D.in[0] = t5c; D.out[0] = E5;  D.n[0] = 512;
               D.in[1] = 0;   D.out[1] = 0;   D.n[1] = 1;
               D.in[2] = 0;   D.out[2] = 0;   D.n[2] = 1;
               D.in[3] = 0;   D.out[3] = 0;   D.n[3] = 1;
    up_blur_kernel<<<dim3(32, 128, 3), blk>>>(D, w0, w1);

    // Final blend, quad-based
    blend_quad_kernel<<<dim3(NE / 32, NE / 8), blk>>>(img, fixs, pyr1, E2, E3, E4, E5, out,
                                                      w0, w1, we0, we1, we2,
                                                      om0, om1, om2, om3, om4);
}

// round 3
// speedup vs baseline: 2.6934x; 2.3999x over previous
#include <cuda_runtime.h>
#include <math.h>

#define HH 2048
#define WW 2048
#define HWFULL (HH * WW)
#define NE 1024              // E maps (half-res expansions) are 1024x1024

// ---------------- static scratch (no allocations allowed) ----------------
__device__ __align__(16) float g_pyr1[3 * 1024 * 1024];
__device__ __align__(16) float g_pyr2[3 * 512 * 512];
__device__ __align__(16) float g_pyr3[3 * 256 * 256];
__device__ __align__(16) float g_pyr4[3 * 128 * 128];
__device__ __align__(16) float g_pyr5[3 * 64 * 64];
__device__ __align__(16) float g_E2[3 * 1024 * 1024];
__device__ __align__(16) float g_E3[3 * 1024 * 1024];
__device__ __align__(16) float g_E4[3 * 1024 * 1024];
__device__ __align__(16) float g_E5[3 * 1024 * 1024];
__device__ __align__(16) float g_t3a[3 * 512 * 512];
__device__ __align__(16) float g_t4a[3 * 256 * 256];
__device__ __align__(16) float g_t4b[3 * 512 * 512];
__device__ __align__(16) float g_t5a[3 * 128 * 128];
__device__ __align__(16) float g_t5b[3 * 256 * 256];
__device__ __align__(16) float g_t5c[3 * 512 * 512];

// ---------------- fused blur (separable 3-tap) + 2x2 mean downsample ------
// out[y][x] = sum_j wv[j] * (De*f[r][2x-1] + Dm*f[r][2x] + Dm*f[r][2x+1] + De*f[r][2x+2])
// expressed with 3 coalesced float2 loads per row.
__global__ void blur_down_kernel(const float* __restrict__ in, float* __restrict__ out,
                                 int no, float De, float Dm) {
    int x = blockIdx.x * blockDim.x + threadIdx.x;
    int y = blockIdx.y * blockDim.y + threadIdx.y;
    int c = blockIdx.z;
    if (x >= no || y >= no) return;
    int ni = 2 * no;
    const float2* ip = (const float2*)(in) + (size_t)c * ni * no;  // no float2 per row
    float acc = 0.f;
#pragma unroll
    for (int j = 0; j < 4; j++) {
        int r = 2 * y - 1 + j;
        if (r < 0 || r >= ni) continue;        // zero padding of the blur
        const float2* row = ip + (size_t)r * no;
        float2 Bc = row[x];
        float a = (x > 0) ? row[x - 1].y : 0.f;
        float d = (x < no - 1) ? row[x + 1].x : 0.f;
        float wj = (j == 0 || j == 3) ? De : Dm;
        acc += wj * (De * a + Dm * Bc.x + Dm * Bc.y + De * d);
    }
    out[(size_t)c * no * no + (size_t)y * no + x] = acc;
}

// ---------------- composite (bilinear x2 upsample -> 3-tap blur) weights ---
__device__ __forceinline__ void ub_weights(int o, int n, float w0, float w1,
                                           int& base, float w[3]) {
    base = (o >> 1) - 1;
    w[0] = w[1] = w[2] = 0.f;
    int n2 = n * 2;
#pragma unroll
    for (int d = -1; d <= 1; ++d) {
        int p = o + d;
        if (p < 0 || p >= n2) continue;
        float bw = (d == 0) ? w0 : w1;
        int i = p >> 1;
        if ((p & 1) == 0) {
            w[i - 1 - base] += 0.25f * bw;
            w[i - base]     += 0.75f * bw;
        } else {
            w[i - base]     += 0.75f * bw;
            w[i + 1 - base] += 0.25f * bw;
        }
    }
}

// per-pixel up+blur (general path, handles borders/clamping)
__device__ float up_pixel(const float* __restrict__ E, int n, int ox, int oy,
                          float w0, float w1) {
    int by, bx;
    float wy[3], wx[3];
    ub_weights(oy, n, w0, w1, by, wy);
    ub_weights(ox, n, w0, w1, bx, wx);
    int ry[3], rx[3];
#pragma unroll
    for (int j = 0; j < 3; j++) {
        ry[j] = min(max(by + j, 0), n - 1);
        rx[j] = min(max(bx + j, 0), n - 1);
    }
    float s = 0.f;
#pragma unroll
    for (int jy = 0; jy < 3; jy++) {
        const float* row = E + (size_t)ry[jy] * n;
        s += wy[jy] * (wx[0] * row[rx[0]] + wx[1] * row[rx[1]] + wx[2] * row[rx[2]]);
    }
    return s;
}

// ---------------- staged up+blur, quad-based ------------------------------
// One thread computes a 2x2 output quad from a shared 3x3 input window with
// parity-constant composite weights (interior); border quads use up_pixel.
struct UpTasks {
    const float* in[4];
    float* out[4];
    int n[4];
};

__global__ void up_blur_quad_kernel(UpTasks T, float w0, float w1,
                                    float we0, float we1, float we2) {
    int task = blockIdx.z / 3;
    int c = blockIdx.z - task * 3;
    int n = T.n[task];                 // input size; output no=2n; quads n x n
    int qx = blockIdx.x * blockDim.x + threadIdx.x;
    int qy = blockIdx.y * blockDim.y + threadIdx.y;
    if (qx >= n || qy >= n) return;
    const float* E = T.in[task] + (size_t)c * n * n;
    int no = 2 * n;
    float* op = T.out[task] + (size_t)c * no * no;

    if (qx == 0 || qx == n - 1 || qy == 0 || qy == n - 1) {
#pragma unroll
        for (int py = 0; py < 2; py++)
#pragma unroll
            for (int px = 0; px < 2; px++) {
                int ox = 2 * qx + px, oy = 2 * qy + py;
                op[(size_t)oy * no + ox] = up_pixel(E, n, ox, oy, w0, w1);
            }
        return;
    }

    const float* pc = E + (size_t)(qy - 1) * n + (qx - 1);
    float he[3], ho[3];
#pragma unroll
    for (int j = 0; j < 3; j++) {
        float a = pc[j * n], b = pc[j * n + 1], d = pc[j * n + 2];
        he[j] = we0 * a + we1 * b + we2 * d;
        ho[j] = we2 * a + we1 * b + we0 * d;
    }
    float2 o0, o1;
    o0.x = we0 * he[0] + we1 * he[1] + we2 * he[2];
    o0.y = we0 * ho[0] + we1 * ho[1] + we2 * ho[2];
    o1.x = we2 * he[0] + we1 * he[1] + we0 * he[2];
    o1.y = we2 * ho[0] + we1 * ho[1] + we0 * ho[2];
    *(float2*)(op + (size_t)(2 * qy) * no + 2 * qx) = o0;
    *(float2*)(op + (size_t)(2 * qy + 1) * no + 2 * qx) = o1;
}

// ---------------- blend helpers --------------------------------------------
__device__ __forceinline__ const float* level_ptr(int l, const float* E1, const float* E2,
                                                  const float* E3, const float* E4,
                                                  const float* E5) {
    const float* p = E1;
    p = (l == 2) ? E2 : p;
    p = (l == 3) ? E3 : p;
    p = (l == 4) ? E4 : p;
    p = (l == 5) ? E5 : p;
    return p;
}

__device__ __forceinline__ float blend_B(int l, float R) {
    float sprev = exp2f((float)(l - 3));
    float ap = sprev * R * (1.0f / 0.248f);
    float tp = expf(-(ap * ap) * 3.0f);
    float tc = 0.f;
    if (l < 5) {
        float ac = 2.0f * ap;
        tc = expf(-(ac * ac) * 3.0f);
    }
    return (0.5f - tc) / (tp - tc + 1e-5f);
}

// per-pixel general blend path (borders / mixed-level quads)
__device__ void pixel_slow(int x, int y, int l, float R,
                           const float* __restrict__ img,
                           const float* __restrict__ E1, const float* __restrict__ E2,
                           const float* __restrict__ E3, const float* __restrict__ E4,
                           const float* __restrict__ E5, float* __restrict__ out,
                           float w0, float w1) {
    int pix = y * WW + x;
    if (l == 0) {
        out[pix] = img[pix];
        out[pix + HWFULL] = img[pix + HWFULL];
        out[pix + 2 * HWFULL] = img[pix + 2 * HWFULL];
        return;
    }
    float B = blend_B(l, R);
    const float* Ecur = level_ptr(l, E1, E2, E3, E4, E5);
    const float* Eprev = level_ptr(l - 1, E1, E2, E3, E4, E5);
#pragma unroll
    for (int c = 0; c < 3; c++) {
        float vc = up_pixel(Ecur + c * NE * NE, NE, x, y, w0, w1);
        float vp = (l == 1) ? img[pix + c * HWFULL]
                            : up_pixel(Eprev + c * NE * NE, NE, x, y, w0, w1);
        out[pix + c * HWFULL] = B * vp + (1.f - B) * vc;
    }
}

// per-quad global-memory fast path (interior quad, uniform level within quad)
__device__ void quad_global(int qx, int qy, int l0, const float B[2][2],
                            const float* __restrict__ img,
                            const float* __restrict__ cur, const float* __restrict__ prv,
                            float* __restrict__ out,
                            float we0, float we1, float we2) {
    int pix0 = (2 * qy) * WW + 2 * qx;
    int wbase = (qy - 1) * NE + (qx - 1);
#pragma unroll
    for (int c = 0; c < 3; c++) {
        const float* pc = cur + c * NE * NE + wbase;
        float he[3], ho[3];
#pragma unroll
        for (int j = 0; j < 3; j++) {
            float a = pc[j * NE], b = pc[j * NE + 1], d = pc[j * NE + 2];
            he[j] = we0 * a + we1 * b + we2 * d;
            ho[j] = we2 * a + we1 * b + we0 * d;
        }
        float vc[2][2];
        vc[0][0] = we0 * he[0] + we1 * he[1] + we2 * he[2];
        vc[0][1] = we0 * ho[0] + we1 * ho[1] + we2 * ho[2];
        vc[1][0] = we2 * he[0] + we1 * he[1] + we0 * he[2];
        vc[1][1] = we2 * ho[0] + we1 * ho[1] + we0 * ho[2];

        float vp[2][2];
        if (l0 == 1) {
            float2 i0 = *(const float2*)(img + pix0 + c * HWFULL);
            float2 i1 = *(const float2*)(img + pix0 + WW + c * HWFULL);
            vp[0][0] = i0.x; vp[0][1] = i0.y; vp[1][0] = i1.x; vp[1][1] = i1.y;
        } else {
            const float* pp = prv + c * NE * NE + wbase;
            float pe[3], po[3];
#pragma unroll
            for (int j = 0; j < 3; j++) {
                float a = pp[j * NE], b = pp[j * NE + 1], d = pp[j * NE + 2];
                pe[j] = we0 * a + we1 * b + we2 * d;
                po[j] = we2 * a + we1 * b + we0 * d;
            }
            vp[0][0] = we0 * pe[0] + we1 * pe[1] + we2 * pe[2];
            vp[0][1] = we0 * po[0] + we1 * po[1] + we2 * po[2];
            vp[1][0] = we2 * pe[0] + we1 * pe[1] + we0 * pe[2];
            vp[1][1] = we2 * po[0] + we1 * po[1] + we0 * po[2];
        }
        float2 o0, o1;
        o0.x = B[0][0] * vp[0][0] + (1.f - B[0][0]) * vc[0][0];
        o0.y = B[0][1] * vp[0][1] + (1.f - B[0][1]) * vc[0][1];
        o1.x = B[1][0] * vp[1][0] + (1.f - B[1][0]) * vc[1][0];
        o1.y = B[1][1] * vp[1][1] + (1.f - B[1][1]) * vc[1][1];
        *(float2*)(out + pix0 + c * HWFULL) = o0;
        *(float2*)(out + pix0 + WW + c * HWFULL) = o1;
    }
}

// ---------------- blend: block-uniform smem fast path ----------------------
#define TQX 32
#define TQY 8
#define TPITCH 34            // 32+2 window cols
#define TROWS 10             // 8+2 window rows

__global__ __launch_bounds__(256)
void blend_quad_kernel(const float* __restrict__ img, const float* __restrict__ fixs,
                       const float* __restrict__ E1, const float* __restrict__ E2,
                       const float* __restrict__ E3, const float* __restrict__ E4,
                       const float* __restrict__ E5, float* __restrict__ out,
                       float w0, float w1, float we0, float we1, float we2,
                       float om0, float om1, float om2, float om3, float om4) {
    __shared__ float s_cur[3][TROWS][TPITCH];
    __shared__ float s_prv[3][TROWS][TPITCH];
    __shared__ int s_ref;

    int tx = threadIdx.x, ty = threadIdx.y;
    int qx = blockIdx.x * TQX + tx;
    int qy = blockIdx.y * TQY + ty;

    float fx[4], fy[4];
#pragma unroll
    for (int k = 0; k < 4; k++) { fx[k] = fixs[2 * k]; fy[k] = fixs[2 * k + 1]; }

    float omega[6] = {om0, om1, om2, om3, om4, 0.f};
    int lv[2][2];
    float Rv[2][2];
#pragma unroll
    for (int py = 0; py < 2; py++)
#pragma unroll
        for (int px = 0; px < 2; px++) {
            float xf = (float)(2 * qx + px), yf = (float)(2 * qy + py);
            float d2 = 3.4e38f;
#pragma unroll
            for (int k = 0; k < 4; k++) {
                float dx = xf - fx[k], dy = yf - fy[k];
                d2 = fminf(d2, dx * dx + dy * dy);
            }
            float theta = sqrtf(d2) * (1.0f / 7.5f);
            float R = 2.5f / (theta + 2.5f);
            Rv[py][px] = R;
            int l = 0;
#pragma unroll
            for (int i = 1; i <= 5; i++)
                if (R >= omega[i] && R <= omega[i - 1]) l = i;
            lv[py][px] = l;
        }

    if (tx == 0 && ty == 0) s_ref = lv[0][0];
    __syncthreads();
    int lref = s_ref;
    bool mine_uniform = (lv[0][0] == lref) && (lv[0][1] == lref) &&
                        (lv[1][0] == lref) && (lv[1][1] == lref);
    int all_uni = __syncthreads_and(mine_uniform ? 1 : 0);
    bool block_border = (blockIdx.x == 0) || (blockIdx.x == gridDim.x - 1) ||
                        (blockIdx.y == 0) || (blockIdx.y == gridDim.y - 1);

    int pix0 = (2 * qy) * WW + 2 * qx;

    if (all_uni && !block_border) {
        if (lref == 0) {
            // uniform pass-through block
#pragma unroll
            for (int c = 0; c < 3; c++) {
                *(float2*)(out + pix0 + c * HWFULL) =
                    *(const float2*)(img + pix0 + c * HWFULL);
                *(float2*)(out + pix0 + WW + c * HWFULL) =
                    *(const float2*)(img + pix0 + WW + c * HWFULL);
            }
            return;
        }
        const float* cur = level_ptr(lref, E1, E2, E3, E4, E5);
        const float* prv = level_ptr(lref - 1, E1, E2, E3, E4, E5);
        int ox0 = blockIdx.x * TQX - 1;     // tile origin in E coords
        int oy0 = blockIdx.y * TQY - 1;
        int tid = ty * TQX + tx;
        int nfill = 3 * TROWS * TPITCH;     // 1020
        for (int i = tid; i < nfill; i += 256) {
            int c = i / (TROWS * TPITCH);
            int rem = i - c * (TROWS * TPITCH);
            int r = rem / TPITCH, col = rem - r * TPITCH;
            size_t g = (size_t)c * NE * NE + (size_t)(oy0 + r) * NE + (ox0 + col);
            s_cur[c][r][col] = cur[g];
            if (lref >= 2) s_prv[c][r][col] = prv[g];
        }
        __syncthreads();

        float B[2][2];
#pragma unroll
        for (int py = 0; py < 2; py++)
#pragma unroll
            for (int px = 0; px < 2; px++)
                B[py][px] = blend_B(lref, Rv[py][px]);

#pragma unroll
        for (int c = 0; c < 3; c++) {
            float he[3], ho[3];
#pragma unroll
            for (int j = 0; j < 3; j++) {
                float a = s_cur[c][ty + j][tx];
                float b = s_cur[c][ty + j][tx + 1];
                float d = s_cur[c][ty + j][tx + 2];
                he[j] = we0 * a + we1 * b + we2 * d;
                ho[j] = we2 * a + we1 * b + we0 * d;
            }
            float vc[2][2];
            vc[0][0] = we0 * he[0] + we1 * he[1] + we2 * he[2];
            vc[0][1] = we0 * ho[0] + we1 * ho[1] + we2 * ho[2];
            vc[1][0] = we2 * he[0] + we1 * he[1] + we0 * he[2];
            vc[1][1] = we2 * ho[0] + we1 * ho[1] + we0 * ho[2];

            float vp[2][2];
            if (lref == 1) {
                float2 i0 = *(const float2*)(img + pix0 + c * HWFULL);
                float2 i1 = *(const float2*)(img + pix0 + WW + c * HWFULL);
                vp[0][0] = i0.x; vp[0][1] = i0.y; vp[1][0] = i1.x; vp[1][1] = i1.y;
            } else {
                float pe[3], po[3];
#pragma unroll
                for (int j = 0; j < 3; j++) {
                    float a = s_prv[c][ty + j][tx];
                    float b = s_prv[c][ty + j][tx + 1];
                    float d = s_prv[c][ty + j][tx + 2];
                    pe[j] = we0 * a + we1 * b + we2 * d;
                    po[j] = we2 * a + we1 * b + we0 * d;
                }
                vp[0][0] = we0 * pe[0] + we1 * pe[1] + we2 * pe[2];
                vp[0][1] = we0 * po[0] + we1 * po[1] + we2 * po[2];
                vp[1][0] = we2 * pe[0] + we1 * pe[1] + we0 * pe[2];
                vp[1][1] = we2 * po[0] + we1 * po[1] + we0 * po[2];
            }
            float2 o0, o1;
            o0.x = B[0][0] * vp[0][0] + (1.f - B[0][0]) * vc[0][0];
            o0.y = B[0][1] * vp[0][1] + (1.f - B[0][1]) * vc[0][1];
            o1.x = B[1][0] * vp[1][0] + (1.f - B[1][0]) * vc[1][0];
            o1.y = B[1][1] * vp[1][1] + (1.f - B[1][1]) * vc[1][1];
            *(float2*)(out + pix0 + c * HWFULL) = o0;
            *(float2*)(out + pix0 + WW + c * HWFULL) = o1;
        }
        return;
    }

    // ---- fallback: per-quad path (global memory) ----
    int l0 = lv[0][0];
    bool uni = (lv[0][1] == l0) && (lv[1][0] == l0) && (lv[1][1] == l0);
    bool qborder = (qx == 0) | (qx >= NE - 1) | (qy == 0) | (qy >= NE - 1);

    if (uni && l0 == 0) {
#pragma unroll
        for (int c = 0; c < 3; c++) {
            *(float2*)(out + pix0 + c * HWFULL) =
                *(const float2*)(img + pix0 + c * HWFULL);
            *(float2*)(out + pix0 + WW + c * HWFULL) =
                *(const float2*)(img + pix0 + WW + c * HWFULL);
        }
        return;
    }
    if (!uni || qborder) {
#pragma unroll
        for (int py = 0; py < 2; py++)
#pragma unroll
            for (int px = 0; px < 2; px++)
                pixel_slow(2 * qx + px, 2 * qy + py, lv[py][px], Rv[py][px],
                           img, E1, E2, E3, E4, E5, out, w0, w1);
        return;
    }
    float B[2][2];
#pragma unroll
    for (int py = 0; py < 2; py++)
#pragma unroll
        for (int px = 0; px < 2; px++)
            B[py][px] = blend_B(l0, Rv[py][px]);
    const float* cur = level_ptr(l0, E1, E2, E3, E4, E5);
    const float* prv = level_ptr(l0 - 1, E1, E2, E3, E4, E5);
    quad_global(qx, qy, l0, B, img, cur, prv, out, we0, we1, we2);
}

// ---------------- host launch ---------------------------------------------
extern "C" void kernel_launch(void* const* d_in, const int* in_sizes, int n_in,
                              void* d_out, int out_size) {
    const float* img = (const float*)d_in[0];
    const float* fixs = (const float*)d_in[1];
    float* out = (float*)d_out;

    float *pyr1, *pyr2, *pyr3, *pyr4, *pyr5, *E2, *E3, *E4, *E5;
    float *t3a, *t4a, *t4b, *t5a, *t5b, *t5c;
    cudaGetSymbolAddress((void**)&pyr1, g_pyr1);
    cudaGetSymbolAddress((void**)&pyr2, g_pyr2);
    cudaGetSymbolAddress((void**)&pyr3, g_pyr3);
    cudaGetSymbolAddress((void**)&pyr4, g_pyr4);
    cudaGetSymbolAddress((void**)&pyr5, g_pyr5);
    cudaGetSymbolAddress((void**)&E2, g_E2);
    cudaGetSymbolAddress((void**)&E3, g_E3);
    cudaGetSymbolAddress((void**)&E4, g_E4);
    cudaGetSymbolAddress((void**)&E5, g_E5);
    cudaGetSymbolAddress((void**)&t3a, g_t3a);
    cudaGetSymbolAddress((void**)&t4a, g_t4a);
    cudaGetSymbolAddress((void**)&t4b, g_t4b);
    cudaGetSymbolAddress((void**)&t5a, g_t5a);
    cudaGetSymbolAddress((void**)&t5b, g_t5b);
    cudaGetSymbolAddress((void**)&t5c, g_t5c);

    // Gaussian taps (w2 ~ 7.5e-15 dropped from taps; kept in normalization)
    double s2 = 2.0 * 0.248 * 0.248;
    double g1 = exp(-1.0 / s2);
    double g2 = exp(-4.0 / s2);
    double nrm = 1.0 + 2.0 * g1 + 2.0 * g2;
    float w0 = (float)(1.0 / nrm);
    float w1 = (float)(g1 / nrm);
    float De = (float)(0.5 * g1 / nrm);
    float Dm = (float)(0.5 * (1.0 + g1) / nrm);
    float we0 = 0.25f * w0 + 0.75f * w1;
    float we1 = 0.75f * w0 + w1;
    float we2 = 0.25f * w1;

    double ob = sqrt(log(2.0) / 3.0) * 0.248;
    float om0 = (float)(ob * 4.0);
    float om1 = (float)(ob * 2.0);
    float om2 = (float)(ob);
    float om3 = (float)(ob * 0.5);
    float om4 = (float)(ob * 0.25);

    dim3 blk(32, 8);
    auto grd = [](int n) { return dim3((n + 31) / 32, (n + 7) / 8, 3); };

    // Gaussian pyramid (fused blur + 2x2 mean, float2-coalesced)
    blur_down_kernel<<<grd(1024), blk>>>(img,  pyr1, 1024, De, Dm);
    blur_down_kernel<<<grd(512),  blk>>>(pyr1, pyr2, 512,  De, Dm);
    blur_down_kernel<<<grd(256),  blk>>>(pyr2, pyr3, 256,  De, Dm);
    blur_down_kernel<<<grd(128),  blk>>>(pyr3, pyr4, 128,  De, Dm);
    blur_down_kernel<<<grd(64),   blk>>>(pyr4, pyr5, 64,   De, Dm);

    // Expansion chains to 1024x1024 (E maps), staged, quad-based
    UpTasks A; A.in[0] = pyr2; A.out[0] = E2;  A.n[0] = 512;
               A.in[1] = pyr3; A.out[1] = t3a; A.n[1] = 256;
               A.in[2] = pyr4; A.out[2] = t4a; A.n[2] = 128;
               A.in[3] = pyr5; A.out[3] = t5a; A.n[3] = 64;
    up_blur_quad_kernel<<<dim3(16, 64, 12), blk>>>(A, w0, w1, we0, we1, we2);

    UpTasks B; B.in[0] = t3a; B.out[0] = E3;  B.n[0] = 512;
               B.in[1] = t4a; B.out[1] = t4b; B.n[1] = 256;
               B.in[2] = t5a; B.out[2] = t5b; B.n[2] = 128;
               B.in[3] = 0;   B.out[3] = 0;   B.n[3] = 1;
    up_blur_quad_kernel<<<dim3(16, 64, 9), blk>>>(B, w0, w1, we0, we1, we2);

    UpTasks C; C.in[0] = t4b; C.out[0] = E4;  C.n[0] = 512;
               C.in[1] = t5b; C.out[1] = t5c; C.n[1] = 256;
               C.in[2] = 0;   C.out[2] = 0;   C.n[2] = 1;
               C.in[3] = 0;   C.out[3] = 0;   C.n[3] = 1;
    up_blur_quad_kernel<<<dim3(16, 64, 6), blk>>>(C, w0, w1, we0, we1, we2);

    UpTasks D; D.in[0] = t5c; D.out[0] = E5;  D.n[0] = 512;
               D.in[1] = 0;   D.out[1] = 0;   D.n[1] = 1;
               D.in[2] = 0;   D.out[2] = 0;   D.n[2] = 1;
               D.in[3] = 0;   D.out[3] = 0;   D.n[3] = 1;
    up_blur_quad_kernel<<<dim3(16, 64, 3), blk>>>(D, w0, w1, we0, we1, we2);

    // Final blend, block-uniform smem fast path
    blend_quad_kernel<<<dim3(NE / 32, NE / 8), blk>>>(img, fixs, pyr1, E2, E3, E4, E5, out,
                                                      w0, w1, we0, we1, we2,
                                                      om0, om1, om2, om3, om4);
}